// round 1
// baseline (speedup 1.0000x reference)
#include <cuda_runtime.h>
#include <math.h>

#define T_  4
#define B_  32
#define N_  196
#define C_  512
#define H_  8
#define HD  64
#define TBc (T_*B_)            // 128
#define M_  (TBc*N_)           // 25088 rows
#define ELEMS ((size_t)M_*C_)  // 12,845,056
#define BNC ((size_t)B_*N_*C_) // per-timestep elements

// ---------------- scratch (device globals: no allocation allowed) ----------------
__device__ float g_buf0[ELEMS];   // y_q  -> attn output (pre attn_lif)
__device__ float g_buf1[ELEMS];   // y_k  -> attn_lif spikes (fp32, proj input)
__device__ float g_buf2[ELEMS];   // y_v  -> proj linear output
__device__ unsigned int g_qbits[(size_t)T_*B_*H_*N_*2];
__device__ unsigned int g_kbits[(size_t)T_*B_*H_*N_*2];
__device__ unsigned int g_vbits[(size_t)T_*B_*H_*N_*2];
__device__ double g_sum[C_];
__device__ double g_sumsq[C_];
__device__ float  g_mean[C_];
__device__ float  g_rstd[C_];

// ---------------- fp32 SGEMM: C[M,N] = A[M,K] @ W[N,K]^T + bias ----------------
__global__ __launch_bounds__(256) void sgemm_nt(
    const float* __restrict__ A, const float* __restrict__ W,
    const float* __restrict__ bias, float* __restrict__ C,
    int M, int N, int K)
{
    __shared__ float As[8][128];
    __shared__ float Bs[8][128];
    const int tid = threadIdx.x;
    const int m0 = blockIdx.y * 128;
    const int n0 = blockIdx.x * 128;
    const int lr = tid >> 1;
    const int lc = (tid & 1) << 2;
    const float* Ap = A + (size_t)(m0 + lr) * K + lc;
    const float* Wp = W + (size_t)(n0 + lr) * K + lc;
    const int tx = tid & 15;   // n-dir
    const int ty = tid >> 4;   // m-dir

    float acc[8][8];
#pragma unroll
    for (int i = 0; i < 8; i++)
#pragma unroll
        for (int j = 0; j < 8; j++) acc[i][j] = 0.f;

    for (int k0 = 0; k0 < K; k0 += 8) {
        float4 a4 = *(const float4*)(Ap + k0);
        float4 b4 = *(const float4*)(Wp + k0);
        __syncthreads();
        As[lc + 0][lr] = a4.x; As[lc + 1][lr] = a4.y;
        As[lc + 2][lr] = a4.z; As[lc + 3][lr] = a4.w;
        Bs[lc + 0][lr] = b4.x; Bs[lc + 1][lr] = b4.y;
        Bs[lc + 2][lr] = b4.z; Bs[lc + 3][lr] = b4.w;
        __syncthreads();
#pragma unroll
        for (int kk = 0; kk < 8; kk++) {
            float4 a0 = *(const float4*)&As[kk][ty * 8];
            float4 a1 = *(const float4*)&As[kk][ty * 8 + 4];
            float4 b0 = *(const float4*)&Bs[kk][tx * 8];
            float4 b1 = *(const float4*)&Bs[kk][tx * 8 + 4];
            float af[8] = {a0.x, a0.y, a0.z, a0.w, a1.x, a1.y, a1.z, a1.w};
            float bf[8] = {b0.x, b0.y, b0.z, b0.w, b1.x, b1.y, b1.z, b1.w};
#pragma unroll
            for (int i = 0; i < 8; i++)
#pragma unroll
                for (int j = 0; j < 8; j++)
                    acc[i][j] += af[i] * bf[j];
        }
    }
#pragma unroll
    for (int i = 0; i < 8; i++) {
        int m = m0 + ty * 8 + i;
        float* cp = C + (size_t)m * N + n0 + tx * 8;
        float4 r0, r1;
        r0.x = acc[i][0] + bias[n0 + tx * 8 + 0];
        r0.y = acc[i][1] + bias[n0 + tx * 8 + 1];
        r0.z = acc[i][2] + bias[n0 + tx * 8 + 2];
        r0.w = acc[i][3] + bias[n0 + tx * 8 + 3];
        r1.x = acc[i][4] + bias[n0 + tx * 8 + 4];
        r1.y = acc[i][5] + bias[n0 + tx * 8 + 5];
        r1.z = acc[i][6] + bias[n0 + tx * 8 + 6];
        r1.w = acc[i][7] + bias[n0 + tx * 8 + 7];
        *(float4*)cp = r0;
        *(float4*)(cp + 4) = r1;
    }
}

// ---------------- BatchNorm statistics (fp64 accumulation) ----------------
__global__ void bn_stats_zero() {
    int c = threadIdx.x;
    g_sum[c] = 0.0; g_sumsq[c] = 0.0;
}

#define ROWSPB 128
__global__ __launch_bounds__(512) void bn_stats_acc(const float* __restrict__ y) {
    int c = threadIdx.x;
    int r0 = blockIdx.x * ROWSPB;
    double s = 0.0, s2 = 0.0;
    for (int r = 0; r < ROWSPB; r++) {
        float v = y[(size_t)(r0 + r) * C_ + c];
        s += (double)v;
        s2 += (double)v * (double)v;
    }
    atomicAdd(&g_sum[c], s);
    atomicAdd(&g_sumsq[c], s2);
}

__global__ void bn_stats_fin() {
    int c = threadIdx.x;
    double mean = g_sum[c] * (1.0 / (double)M_);
    double var = g_sumsq[c] * (1.0 / (double)M_) - mean * mean;
    float vf = (float)var;
    g_mean[c] = (float)mean;
    g_rstd[c] = (float)(1.0 / sqrt((double)(vf + 1e-5f)));
}

// ---------------- BN + LIF (tau=2, v_th=1) + bit-pack spikes ----------------
__global__ __launch_bounds__(512) void bn_lif_pack(
    const float* __restrict__ y, const float* __restrict__ gamma,
    const float* __restrict__ beta, unsigned int* __restrict__ bits)
{
    int c = threadIdx.x;
    int bn = blockIdx.x;              // b*N_ + n
    float mean = g_mean[c], r = g_rstd[c], g = gamma[c], be = beta[c];
    int b = bn / N_, n = bn % N_;
    int h = c >> 6, lane = c & 31, half = (c >> 5) & 1;
    float v = 0.f;
    for (int t = 0; t < T_; t++) {
        float xv = y[((size_t)t * (B_ * N_) + bn) * C_ + c];
        float xb = __fadd_rn(__fmul_rn(__fmul_rn(__fsub_rn(xv, mean), r), g), be);
        v = __fadd_rn(v, __fmul_rn(__fsub_rn(xb, v), 0.5f));
        unsigned sp = (v >= 1.0f) ? 1u : 0u;
        if (sp) v = 0.f;
        unsigned bal = __ballot_sync(0xffffffffu, sp);
        if (lane == 0)
            bits[((size_t)((t * B_ + b) * H_ + h) * N_ + n) * 2 + half] = bal;
    }
}

// ---------------- Attention: exact integer math on binary spikes ----------------
// per block: one (t,b,h). S = popc(q&k) masked; O = S@V via dp4a. out *= 0.125.
__global__ __launch_bounds__(256) void attn_kernel(
    const float* __restrict__ policy,
    const unsigned int* __restrict__ qbi, const unsigned int* __restrict__ kbi,
    const unsigned int* __restrict__ vbi, float* __restrict__ out)
{
    __shared__ uint2 qs[N_];
    __shared__ uint2 ks[N_];
    __shared__ int vT[HD][53];       // bytes: vT[d][m] = bit d of v[m]; pad m to 212
    __shared__ int srow[8][53];      // per-warp masked S row (bytes)
    __shared__ unsigned char keep[N_];

    int blk = blockIdx.x;
    int h = blk % H_;
    int tb = blk / H_;
    int tid = threadIdx.x;

    const uint2* qp = (const uint2*)qbi + (size_t)(tb * H_ + h) * N_;
    const uint2* kp = (const uint2*)kbi + (size_t)(tb * H_ + h) * N_;
    for (int i = tid; i < N_; i += 256) {
        qs[i] = qp[i];
        ks[i] = kp[i];
        keep[i] = (policy[(size_t)tb * N_ + i] != 0.0f) ? 1 : 0;
    }
    const unsigned int* vp = vbi + (size_t)(tb * H_ + h) * N_ * 2;
    for (int i = tid; i < N_ * 2; i += 256) {
        unsigned w = vp[i];
        int m = i >> 1, dbase = (i & 1) * 32;
#pragma unroll
        for (int j = 0; j < 32; j++)
            ((unsigned char*)vT[dbase + j])[m] = (unsigned char)((w >> j) & 1u);
    }
    __syncthreads();

    int warp = tid >> 5, lane = tid & 31;
    for (int n = warp; n < N_; n += 8) {
        uint2 q = qs[n];
        for (int m = lane; m < 212; m += 32) {
            int s = 0;
            if (m < N_) {
                uint2 kk = ks[m];
                s = __popc(q.x & kk.x) + __popc(q.y & kk.y);
                if (!(keep[m] || (m == n))) s = 0;
            }
            ((unsigned char*)srow[warp])[m] = (unsigned char)s;
        }
        __syncwarp();
        int acc0 = 0, acc1 = 0;
#pragma unroll
        for (int q4 = 0; q4 < 53; q4++) {
            int sv = srow[warp][q4];
            acc0 = __dp4a(sv, vT[lane][q4], acc0);
            acc1 = __dp4a(sv, vT[lane + 32][q4], acc1);
        }
        float* op = out + ((size_t)tb * N_ + n) * C_ + h * HD;
        op[lane]      = (float)acc0 * 0.125f;
        op[lane + 32] = (float)acc1 * 0.125f;
        __syncwarp();
    }
}

// ---------------- attn LIF (v_th = 0.5), spikes as fp32 for proj GEMM ----------------
__global__ void lif_attn(const float* __restrict__ in, float* __restrict__ outs) {
    size_t idx = (size_t)blockIdx.x * blockDim.x + threadIdx.x;
    if (idx >= BNC) return;
    float v = 0.f;
    for (int t = 0; t < T_; t++) {
        float xv = in[(size_t)t * BNC + idx];
        v = __fadd_rn(v, __fmul_rn(__fsub_rn(xv, v), 0.5f));
        unsigned sp = (v >= 0.5f) ? 1u : 0u;
        outs[(size_t)t * BNC + idx] = sp ? 1.0f : 0.0f;
        if (sp) v = 0.f;
    }
}

// ---------------- final BN + LIF writing fp32 spikes ----------------
__global__ __launch_bounds__(512) void bn_lif_out(
    const float* __restrict__ y, const float* __restrict__ gamma,
    const float* __restrict__ beta, float* __restrict__ out)
{
    int c = threadIdx.x;
    int bn = blockIdx.x;
    float mean = g_mean[c], r = g_rstd[c], g = gamma[c], be = beta[c];
    float v = 0.f;
    for (int t = 0; t < T_; t++) {
        float xv = y[((size_t)t * (B_ * N_) + bn) * C_ + c];
        float xb = __fadd_rn(__fmul_rn(__fmul_rn(__fsub_rn(xv, mean), r), g), be);
        v = __fadd_rn(v, __fmul_rn(__fsub_rn(xb, v), 0.5f));
        unsigned sp = (v >= 1.0f) ? 1u : 0u;
        if (sp) v = 0.f;
        out[((size_t)t * (B_ * N_) + bn) * C_ + c] = sp ? 1.0f : 0.0f;
    }
}

// ---------------- launch ----------------
extern "C" void kernel_launch(void* const* d_in, const int* in_sizes, int n_in,
                              void* d_out, int out_size)
{
    const float* x      = (const float*)d_in[0];
    const float* policy = (const float*)d_in[1];
    const float* qw  = (const float*)d_in[2];
    const float* qb  = (const float*)d_in[3];
    const float* qg  = (const float*)d_in[4];
    const float* qbe = (const float*)d_in[5];
    const float* kw  = (const float*)d_in[6];
    const float* kb  = (const float*)d_in[7];
    const float* kg  = (const float*)d_in[8];
    const float* kbe = (const float*)d_in[9];
    const float* vw  = (const float*)d_in[10];
    const float* vb  = (const float*)d_in[11];
    const float* vg  = (const float*)d_in[12];
    const float* vbe = (const float*)d_in[13];
    const float* pw  = (const float*)d_in[14];
    const float* pb  = (const float*)d_in[15];
    const float* pg  = (const float*)d_in[16];
    const float* pbe = (const float*)d_in[17];
    float* out = (float*)d_out;

    float *b0, *b1, *b2;
    unsigned int *QB, *KB, *VB;
    cudaGetSymbolAddress((void**)&b0, g_buf0);
    cudaGetSymbolAddress((void**)&b1, g_buf1);
    cudaGetSymbolAddress((void**)&b2, g_buf2);
    cudaGetSymbolAddress((void**)&QB, g_qbits);
    cudaGetSymbolAddress((void**)&KB, g_kbits);
    cudaGetSymbolAddress((void**)&VB, g_vbits);

    dim3 gg(C_ / 128, M_ / 128);   // (4, 196)
    const int statBlocks = M_ / ROWSPB;   // 196

    // --- q branch ---
    sgemm_nt<<<gg, 256>>>(x, qw, qb, b0, M_, C_, C_);
    bn_stats_zero<<<1, C_>>>();
    bn_stats_acc<<<statBlocks, C_>>>(b0);
    bn_stats_fin<<<1, C_>>>();
    bn_lif_pack<<<B_ * N_, C_>>>(b0, qg, qbe, QB);
    // --- k branch ---
    sgemm_nt<<<gg, 256>>>(x, kw, kb, b1, M_, C_, C_);
    bn_stats_zero<<<1, C_>>>();
    bn_stats_acc<<<statBlocks, C_>>>(b1);
    bn_stats_fin<<<1, C_>>>();
    bn_lif_pack<<<B_ * N_, C_>>>(b1, kg, kbe, KB);
    // --- v branch ---
    sgemm_nt<<<gg, 256>>>(x, vw, vb, b2, M_, C_, C_);
    bn_stats_zero<<<1, C_>>>();
    bn_stats_acc<<<statBlocks, C_>>>(b2);
    bn_stats_fin<<<1, C_>>>();
    bn_lif_pack<<<B_ * N_, C_>>>(b2, vg, vbe, VB);

    // --- attention (exact integer) ---
    attn_kernel<<<T_ * B_ * H_, 256>>>(policy, QB, KB, VB, b0);
    lif_attn<<<(int)((BNC + 255) / 256), 256>>>(b0, b1);

    // --- projection ---
    sgemm_nt<<<gg, 256>>>(b1, pw, pb, b2, M_, C_, C_);
    bn_stats_zero<<<1, C_>>>();
    bn_stats_acc<<<statBlocks, C_>>>(b2);
    bn_stats_fin<<<1, C_>>>();
    bn_lif_out<<<B_ * N_, C_>>>(b2, pg, pbe, out);
}

// round 4
// speedup vs baseline: 1.8625x; 1.8625x over previous
#include <cuda_runtime.h>
#include <cuda_fp16.h>
#include <cstdint>
#include <math.h>

#define T_  4
#define B_  32
#define N_  196
#define C_  512
#define H_  8
#define HD  64
#define M_  (T_*B_*N_)          // 25088
#define ELEMS ((size_t)M_*C_)   // 12,845,056
#define BNC ((size_t)B_*N_*C_)

// ---------------- scratch (device globals) ----------------
__device__ float g_y[ELEMS];                    // GEMM output (reused q,k,v,proj)
__device__ float g_attn[ELEMS];                 // attention output
__device__ __half g_x0[ELEMS], g_x1[ELEMS];     // x fp16 splits
__device__ __half g_pA[ELEMS];                  // attn spikes (fp16, exact 0/1)
__device__ __half g_w0[C_*C_], g_w1[C_*C_];     // weight fp16 splits
__device__ unsigned int g_qbits[(size_t)T_*B_*H_*N_*2];
__device__ unsigned int g_kbits[(size_t)T_*B_*H_*N_*2];
__device__ unsigned int g_vbits[(size_t)T_*B_*H_*N_*2];
__device__ double g_sum[C_];
__device__ double g_sumsq[C_];
__device__ float  g_mean[C_];
__device__ float  g_rstd[C_];

// ---------------- helpers ----------------
static __device__ __forceinline__ uint32_t s2u(const void* p) {
    uint32_t a;
    asm("{ .reg .u64 t; cvta.to.shared.u64 t, %1; cvt.u32.u64 %0, t; }" : "=r"(a) : "l"(p));
    return a;
}
static __device__ __forceinline__ void cpa16(uint32_t dst, const void* src) {
    asm volatile("cp.async.cg.shared.global [%0], [%1], 16;" :: "r"(dst), "l"(src));
}
static __device__ __forceinline__ void ldmx4(uint32_t* r, uint32_t addr) {
    asm volatile("ldmatrix.sync.aligned.m8n8.x4.shared.b16 {%0,%1,%2,%3}, [%4];"
                 : "=r"(r[0]), "=r"(r[1]), "=r"(r[2]), "=r"(r[3]) : "r"(addr));
}
static __device__ __forceinline__ void ldmx2(uint32_t* r, uint32_t addr) {
    asm volatile("ldmatrix.sync.aligned.m8n8.x2.shared.b16 {%0,%1}, [%2];"
                 : "=r"(r[0]), "=r"(r[1]) : "r"(addr));
}
static __device__ __forceinline__ void mma16816(float* c, const uint32_t* a,
                                                const uint32_t* b) {
    asm volatile(
        "mma.sync.aligned.m16n8k16.row.col.f32.f16.f16.f32 "
        "{%0,%1,%2,%3}, {%4,%5,%6,%7}, {%8,%9}, {%0,%1,%2,%3};"
        : "+f"(c[0]), "+f"(c[1]), "+f"(c[2]), "+f"(c[3])
        : "r"(a[0]), "r"(a[1]), "r"(a[2]), "r"(a[3]), "r"(b[0]), "r"(b[1]));
}

// ---------------- fp16 split-GEMM on mma.sync ----------------
// Y[M,512] = A0@B0^T + A0@B1^T + (doA1? A1@B0^T) + bias.  A[M,512], B[512,512].
// 128x128 tile, BK=32, 256 thr, 8 warps (2m x 4n), cp.async double buffer.
#define APAD 40          // halfs per smem row (80 B)
#define TILE_H (128*APAD)
#define GSMEM (2*4*TILE_H*sizeof(__half))   // 81920 B

__global__ __launch_bounds__(256) void gemm_fp16_mma(
    const __half* __restrict__ A0, const __half* __restrict__ A1,
    const __half* __restrict__ B0, const __half* __restrict__ B1,
    const float* __restrict__ bias, float* __restrict__ Y, int doA1)
{
    extern __shared__ __half sm[];
    const int tid = threadIdx.x;
    const int wid = tid >> 5, lane = tid & 31;
    const int m0 = blockIdx.y * 128, n0 = blockIdx.x * 128;
    const int warp_m = wid & 1, warp_n = wid >> 1;

    const __half* gsrc[4] = {A0 + (size_t)m0 * C_, A1 + (size_t)m0 * C_,
                             B0 + (size_t)n0 * C_, B1 + (size_t)n0 * C_};
    const int row = tid >> 1;
    const int cb = (tid & 1) * 2;        // chunk base (0 or 2), chunk = 8 halfs

    // preload stage 0
#pragma unroll
    for (int o = 0; o < 4; o++) {
        if (o == 1 && !doA1) continue;
        uint32_t dst = s2u(sm + (size_t)o * TILE_H + row * APAD + cb * 8);
        const __half* src = gsrc[o] + (size_t)row * C_ + cb * 8;
        cpa16(dst, src);
        cpa16(dst + 16, src + 8);
    }
    asm volatile("cp.async.commit_group;");

    float acc[4][4][4];
#pragma unroll
    for (int i = 0; i < 4; i++)
#pragma unroll
        for (int j = 0; j < 4; j++)
#pragma unroll
            for (int k = 0; k < 4; k++) acc[i][j][k] = 0.f;

    for (int kc = 0; kc < 16; kc++) {
        asm volatile("cp.async.wait_group 0;");
        __syncthreads();
        const int s = kc & 1;
        if (kc + 1 < 16) {
            int k0n = (kc + 1) * 32;
#pragma unroll
            for (int o = 0; o < 4; o++) {
                if (o == 1 && !doA1) continue;
                uint32_t dst = s2u(sm + (size_t)((s ^ 1) * 4 + o) * TILE_H +
                                   row * APAD + cb * 8);
                const __half* src = gsrc[o] + (size_t)row * C_ + k0n + cb * 8;
                cpa16(dst, src);
                cpa16(dst + 16, src + 8);
            }
            asm volatile("cp.async.commit_group;");
        }
        const __half* As0 = sm + (size_t)(s * 4 + 0) * TILE_H;
        const __half* As1 = sm + (size_t)(s * 4 + 1) * TILE_H;
        const __half* Bs0 = sm + (size_t)(s * 4 + 2) * TILE_H;
        const __half* Bs1 = sm + (size_t)(s * 4 + 3) * TILE_H;
#pragma unroll
        for (int j = 0; j < 2; j++) {            // two k16 per BK=32
            uint32_t b0f[4][2], b1f[4][2];
            {
                int r = warp_n * 32 + (lane & 7);
                int col = j * 16 + ((lane >> 3) & 1) * 8;
#pragma unroll
                for (int nt = 0; nt < 4; nt++) {
                    ldmx2(b0f[nt], s2u(Bs0 + (r + nt * 8) * APAD + col));
                    ldmx2(b1f[nt], s2u(Bs1 + (r + nt * 8) * APAD + col));
                }
            }
#pragma unroll
            for (int mt = 0; mt < 4; mt++) {
                int r = warp_m * 64 + mt * 16 + (lane & 15);
                int col = j * 16 + (lane >> 4) * 8;
                uint32_t a0f[4], a1f[4];
                ldmx4(a0f, s2u(As0 + r * APAD + col));
                if (doA1) ldmx4(a1f, s2u(As1 + r * APAD + col));
#pragma unroll
                for (int nt = 0; nt < 4; nt++) {
                    mma16816(acc[mt][nt], a0f, b0f[nt]);
                    mma16816(acc[mt][nt], a0f, b1f[nt]);
                    if (doA1) mma16816(acc[mt][nt], a1f, b0f[nt]);
                }
            }
        }
    }

    // epilogue: direct gmem writes + bias
#pragma unroll
    for (int mt = 0; mt < 4; mt++) {
#pragma unroll
        for (int nt = 0; nt < 4; nt++) {
            int rr = m0 + warp_m * 64 + mt * 16 + (lane >> 2);
            int cc = n0 + warp_n * 32 + nt * 8 + (lane & 3) * 2;
            float b0v = bias[cc], b1v = bias[cc + 1];
            float* y0 = Y + (size_t)rr * C_ + cc;
            y0[0] = acc[mt][nt][0] + b0v;
            y0[1] = acc[mt][nt][1] + b1v;
            float* y1 = Y + (size_t)(rr + 8) * C_ + cc;
            y1[0] = acc[mt][nt][2] + b0v;
            y1[1] = acc[mt][nt][3] + b1v;
        }
    }
}

// ---------------- fp32 -> 2x fp16 split (Dekker) ----------------
__global__ void split2_k(const float* __restrict__ in, size_t n,
                         __half* __restrict__ o0, __half* __restrict__ o1)
{
    size_t i = (size_t)blockIdx.x * blockDim.x + threadIdx.x;
    if (i >= n) return;
    float x = in[i];
    __half h0 = __float2half_rn(x);
    float r1 = __fsub_rn(x, __half2float(h0));
    __half h1 = __float2half_rn(r1);
    o0[i] = h0; o1[i] = h1;
}

// ---------------- BatchNorm statistics (fp64 accumulation) ----------------
__global__ void bn_stats_zero() {
    int c = threadIdx.x;
    g_sum[c] = 0.0; g_sumsq[c] = 0.0;
}
#define ROWSPB 128
__global__ __launch_bounds__(512) void bn_stats_acc(const float* __restrict__ y) {
    int c = threadIdx.x;
    int r0 = blockIdx.x * ROWSPB;
    double s = 0.0, s2 = 0.0;
    for (int r = 0; r < ROWSPB; r++) {
        float v = y[(size_t)(r0 + r) * C_ + c];
        s += (double)v;
        s2 += (double)v * (double)v;
    }
    atomicAdd(&g_sum[c], s);
    atomicAdd(&g_sumsq[c], s2);
}
__global__ void bn_stats_fin() {
    int c = threadIdx.x;
    double mean = g_sum[c] * (1.0 / (double)M_);
    double var = g_sumsq[c] * (1.0 / (double)M_) - mean * mean;
    float vf = (float)var;
    g_mean[c] = (float)mean;
    g_rstd[c] = (float)(1.0 / sqrt((double)(vf + 1e-5f)));
}

// ---------------- BN + LIF (tau=2, v_th=1) + bit-pack ----------------
__global__ __launch_bounds__(512) void bn_lif_pack(
    const float* __restrict__ y, const float* __restrict__ gamma,
    const float* __restrict__ beta, unsigned int* __restrict__ bits)
{
    int c = threadIdx.x;
    int bn = blockIdx.x;
    float mean = g_mean[c], r = g_rstd[c], g = gamma[c], be = beta[c];
    int b = bn / N_, n = bn % N_;
    int h = c >> 6, lane = c & 31, half = (c >> 5) & 1;
    float v = 0.f;
    for (int t = 0; t < T_; t++) {
        float xv = y[((size_t)t * (B_ * N_) + bn) * C_ + c];
        float xb = __fadd_rn(__fmul_rn(__fmul_rn(__fsub_rn(xv, mean), r), g), be);
        v = __fadd_rn(v, __fmul_rn(__fsub_rn(xb, v), 0.5f));
        unsigned sp = (v >= 1.0f) ? 1u : 0u;
        if (sp) v = 0.f;
        unsigned bal = __ballot_sync(0xffffffffu, sp);
        if (lane == 0)
            bits[((size_t)((t * B_ + b) * H_ + h) * N_ + n) * 2 + half] = bal;
    }
}

// ---------------- Attention: exact integer math on binary spikes ----------------
__global__ __launch_bounds__(256) void attn_kernel(
    const float* __restrict__ policy,
    const unsigned int* __restrict__ qbi, const unsigned int* __restrict__ kbi,
    const unsigned int* __restrict__ vbi, float* __restrict__ out)
{
    __shared__ uint2 qs[N_];
    __shared__ uint2 ks[N_];
    __shared__ int vT[HD][53];
    __shared__ int srow[8][53];
    __shared__ unsigned char keep[N_];

    int blk = blockIdx.x;
    int h = blk % H_;
    int tb = blk / H_;
    int tid = threadIdx.x;

    const uint2* qp = (const uint2*)qbi + (size_t)(tb * H_ + h) * N_;
    const uint2* kp = (const uint2*)kbi + (size_t)(tb * H_ + h) * N_;
    for (int i = tid; i < N_; i += 256) {
        qs[i] = qp[i];
        ks[i] = kp[i];
        keep[i] = (policy[(size_t)tb * N_ + i] != 0.0f) ? 1 : 0;
    }
    const unsigned int* vp = vbi + (size_t)(tb * H_ + h) * N_ * 2;
    for (int i = tid; i < N_ * 2; i += 256) {
        unsigned w = vp[i];
        int m = i >> 1, dbase = (i & 1) * 32;
#pragma unroll
        for (int j = 0; j < 32; j++)
            ((unsigned char*)vT[dbase + j])[m] = (unsigned char)((w >> j) & 1u);
    }
    __syncthreads();

    int warp = tid >> 5, lane = tid & 31;
    for (int n = warp; n < N_; n += 8) {
        uint2 q = qs[n];
        for (int m = lane; m < 212; m += 32) {
            int s = 0;
            if (m < N_) {
                uint2 kk = ks[m];
                s = __popc(q.x & kk.x) + __popc(q.y & kk.y);
                if (!(keep[m] || (m == n))) s = 0;
            }
            ((unsigned char*)srow[warp])[m] = (unsigned char)s;
        }
        __syncwarp();
        int acc0 = 0, acc1 = 0;
#pragma unroll
        for (int q4 = 0; q4 < 53; q4++) {
            int sv = srow[warp][q4];
            acc0 = __dp4a(sv, vT[lane][q4], acc0);
            acc1 = __dp4a(sv, vT[lane + 32][q4], acc1);
        }
        float* op = out + ((size_t)tb * N_ + n) * C_ + h * HD;
        op[lane]      = (float)acc0 * 0.125f;
        op[lane + 32] = (float)acc1 * 0.125f;
        __syncwarp();
    }
}

// ---------------- attn LIF (v_th=0.5) -> fp16 spikes (exact) ----------------
__global__ void lif_attn(const float* __restrict__ in, __half* __restrict__ outs) {
    size_t idx = (size_t)blockIdx.x * blockDim.x + threadIdx.x;
    if (idx >= BNC) return;
    float v = 0.f;
    const __half one = __float2half(1.0f);
    const __half zero = __float2half(0.0f);
    for (int t = 0; t < T_; t++) {
        float xv = in[(size_t)t * BNC + idx];
        v = __fadd_rn(v, __fmul_rn(__fsub_rn(xv, v), 0.5f));
        unsigned sp = (v >= 0.5f) ? 1u : 0u;
        outs[(size_t)t * BNC + idx] = sp ? one : zero;
        if (sp) v = 0.f;
    }
}

// ---------------- final BN + LIF writing fp32 spikes ----------------
__global__ __launch_bounds__(512) void bn_lif_out(
    const float* __restrict__ y, const float* __restrict__ gamma,
    const float* __restrict__ beta, float* __restrict__ out)
{
    int c = threadIdx.x;
    int bn = blockIdx.x;
    float mean = g_mean[c], r = g_rstd[c], g = gamma[c], be = beta[c];
    float v = 0.f;
    for (int t = 0; t < T_; t++) {
        float xv = y[((size_t)t * (B_ * N_) + bn) * C_ + c];
        float xb = __fadd_rn(__fmul_rn(__fmul_rn(__fsub_rn(xv, mean), r), g), be);
        v = __fadd_rn(v, __fmul_rn(__fsub_rn(xb, v), 0.5f));
        unsigned sp = (v >= 1.0f) ? 1u : 0u;
        if (sp) v = 0.f;
        out[((size_t)t * (B_ * N_) + bn) * C_ + c] = sp ? 1.0f : 0.0f;
    }
}

// ---------------- launch ----------------
extern "C" void kernel_launch(void* const* d_in, const int* in_sizes, int n_in,
                              void* d_out, int out_size)
{
    const float* x      = (const float*)d_in[0];
    const float* policy = (const float*)d_in[1];
    const float* qw  = (const float*)d_in[2];
    const float* qb  = (const float*)d_in[3];
    const float* qg  = (const float*)d_in[4];
    const float* qbe = (const float*)d_in[5];
    const float* kw  = (const float*)d_in[6];
    const float* kb  = (const float*)d_in[7];
    const float* kg  = (const float*)d_in[8];
    const float* kbe = (const float*)d_in[9];
    const float* vw  = (const float*)d_in[10];
    const float* vb  = (const float*)d_in[11];
    const float* vg  = (const float*)d_in[12];
    const float* vbe = (const float*)d_in[13];
    const float* pw  = (const float*)d_in[14];
    const float* pb  = (const float*)d_in[15];
    const float* pg  = (const float*)d_in[16];
    const float* pbe = (const float*)d_in[17];
    float* out = (float*)d_out;

    float *Y, *AT;
    __half *X0, *X1, *PA, *W0, *W1;
    unsigned int *QB, *KB, *VB;
    cudaGetSymbolAddress((void**)&Y,  g_y);
    cudaGetSymbolAddress((void**)&AT, g_attn);
    cudaGetSymbolAddress((void**)&X0, g_x0);
    cudaGetSymbolAddress((void**)&X1, g_x1);
    cudaGetSymbolAddress((void**)&PA, g_pA);
    cudaGetSymbolAddress((void**)&W0, g_w0);
    cudaGetSymbolAddress((void**)&W1, g_w1);
    cudaGetSymbolAddress((void**)&QB, g_qbits);
    cudaGetSymbolAddress((void**)&KB, g_kbits);
    cudaGetSymbolAddress((void**)&VB, g_vbits);

    cudaFuncSetAttribute(gemm_fp16_mma, cudaFuncAttributeMaxDynamicSharedMemorySize,
                         (int)GSMEM);

    dim3 gG(C_ / 128, M_ / 128);     // (4, 196)
    const int statBlocks = M_ / ROWSPB;
    const size_t WELEMS = (size_t)C_ * C_;

    // split x once (shared by q,k,v)
    split2_k<<<(int)((ELEMS + 511) / 512), 512>>>(x, ELEMS, X0, X1);

    struct { const float *w, *b, *g, *be; unsigned int* bits; } br[3] = {
        {qw, qb, qg, qbe, QB}, {kw, kb, kg, kbe, KB}, {vw, vb, vg, vbe, VB}};
    for (int i = 0; i < 3; i++) {
        split2_k<<<(int)((WELEMS + 511) / 512), 512>>>(br[i].w, WELEMS, W0, W1);
        gemm_fp16_mma<<<gG, 256, GSMEM>>>(X0, X1, W0, W1, br[i].b, Y, 1);
        bn_stats_zero<<<1, C_>>>();
        bn_stats_acc<<<statBlocks, C_>>>(Y);
        bn_stats_fin<<<1, C_>>>();
        bn_lif_pack<<<B_ * N_, C_>>>(Y, br[i].g, br[i].be, br[i].bits);
    }

    // attention (exact integer) + attn LIF
    attn_kernel<<<T_ * B_ * H_, 256>>>(policy, QB, KB, VB, AT);
    lif_attn<<<(int)((BNC + 255) / 256), 256>>>(AT, PA);

    // projection: A binary (exact fp16) x 2 weight splits
    split2_k<<<(int)((WELEMS + 511) / 512), 512>>>(pw, WELEMS, W0, W1);
    gemm_fp16_mma<<<gG, 256, GSMEM>>>(PA, PA, W0, W1, pb, Y, 0);
    bn_stats_zero<<<1, C_>>>();
    bn_stats_acc<<<statBlocks, C_>>>(Y);
    bn_stats_fin<<<1, C_>>>();
    bn_lif_out<<<B_ * N_, C_>>>(Y, pg, pbe, out);
}